// round 3
// baseline (speedup 1.0000x reference)
#include <cuda_runtime.h>
#include <math.h>

#define BB 2
#define TT 1024
#define DD 128
#define HH 64
// DH = 2

// Scratch (allocation-free contract: __device__ globals)
__device__ float g_xT[DD * BB * TT];      // xT[k][t_glob], t_glob = b*1024+t
__device__ float g_WoT[DD * DD];          // WoT[k][j] = Wo[j][k]
__device__ float g_AO[BB * TT * DD];      // attention output, row-major [t_glob][d]

__device__ __forceinline__ float ex2f(float x) {
    float y;
    asm("ex2.approx.ftz.f32 %0, %1;" : "=f"(y) : "f"(x));
    return y;
}

// ---------------------------------------------------------------------------
// Transpose kernel: xT[k][t] = x[t][k] (2048x128 -> 128x2048)
//                   WoT[k][j] = Wo[j][k] (128x128)
// grid (68, 4), block (32, 8). bx<64 -> x tiles, bx>=64 -> Wo tiles.
// ---------------------------------------------------------------------------
__global__ void __launch_bounds__(256) transpose_kernel(const float* __restrict__ x,
                                                        const float* __restrict__ Wo) {
    __shared__ float t[32][33];
    const int bx = blockIdx.x;
    const int by = blockIdx.y;
    const int tx = threadIdx.x;
    const int ty = threadIdx.y;

    const float* src;
    float* dst;
    int row0, col0, ld_dst;
    if (bx < 64) {
        src = x; dst = g_xT; row0 = bx * 32; col0 = by * 32; ld_dst = BB * TT;
    } else {
        src = Wo; dst = g_WoT; row0 = (bx - 64) * 32; col0 = by * 32; ld_dst = DD;
    }

    #pragma unroll
    for (int i = 0; i < 4; i++)
        t[ty + 8 * i][tx] = src[(row0 + ty + 8 * i) * DD + col0 + tx];
    __syncthreads();
    #pragma unroll
    for (int i = 0; i < 4; i++)
        dst[(col0 + ty + 8 * i) * ld_dst + row0 + tx] = t[tx][ty + 8 * i];
}

// ---------------------------------------------------------------------------
// Fused QKV-projection + causal attention. One block per (b,h), 512 threads.
// Thread tid owns rows/queries {tid, 1023-tid} (1025 keys total -> balanced).
// qkv phase: 6 dots per row from xT (coalesced) with per-head weights in smem.
// attn phase: single-pass softmax (no max subtraction -- scores bounded),
//             K/V interleaved as float4 in smem -> 1 LDS.128 per key.
// ---------------------------------------------------------------------------
__global__ void __launch_bounds__(512) fused_attn_kernel(const float* __restrict__ Wq,
                                                         const float* __restrict__ Wk,
                                                         const float* __restrict__ Wv) {
    __shared__ float4 sKV[TT];        // (k0, k1, v0, v1) per position: 16 KB
    __shared__ float4 w8v[DD * 2];    // per k: [0]=(wq0,wq1,wk0,wk1) [1]=(wv0,wv1,0,0)

    const int tid = threadIdx.x;
    const int b = blockIdx.x >> 6;
    const int h = blockIdx.x & 63;
    const int tbase = b * TT;

    // Load the 6 weight rows for this head into smem (w8 layout, stride 8 floats)
    {
        float* w8f = reinterpret_cast<float*>(w8v);
        for (int i = tid; i < DD * 6; i += 512) {
            const int o = i >> 7;       // 0..5
            const int k = i & 127;
            const float* W = (o < 2) ? Wq : (o < 4) ? Wk : Wv;
            w8f[k * 8 + o] = W[(2 * h + (o & 1)) * DD + k];
        }
    }
    __syncthreads();

    // fold 1/(sqrt(DH)*temperature) and log2(e) into the query
    const float cf = 1.4426950408889634f / (1.4142135623730951f * 0.8f);

    float q_s[2][2];

    // ---- QKV phase: thread computes Q/K/V for its 2 rows ----
    #pragma unroll
    for (int ri = 0; ri < 2; ri++) {
        const int r = ri ? (TT - 1 - tid) : tid;
        const float* __restrict__ xcol = g_xT + tbase + r;   // element k at xcol[k*2048]

        float a0 = 0.f, a1 = 0.f, a2 = 0.f, a3 = 0.f, a4 = 0.f, a5 = 0.f;
        #pragma unroll
        for (int kc = 0; kc < 8; kc++) {
            float xb[16];
            #pragma unroll
            for (int u = 0; u < 16; u++)
                xb[u] = xcol[(kc * 16 + u) * (BB * TT)];
            #pragma unroll
            for (int u = 0; u < 16; u++) {
                const int k = kc * 16 + u;
                const float4 wA = w8v[k * 2];
                const float4 wB = w8v[k * 2 + 1];
                a0 = fmaf(xb[u], wA.x, a0);
                a1 = fmaf(xb[u], wA.y, a1);
                a2 = fmaf(xb[u], wA.z, a2);
                a3 = fmaf(xb[u], wA.w, a3);
                a4 = fmaf(xb[u], wB.x, a4);
                a5 = fmaf(xb[u], wB.y, a5);
            }
        }
        sKV[r] = make_float4(a2, a3, a4, a5);
        q_s[ri][0] = a0 * cf;
        q_s[ri][1] = a1 * cf;
    }
    __syncthreads();

    // ---- Attention phase: single pass, no max subtraction ----
    float2* __restrict__ Op = reinterpret_cast<float2*>(g_AO);
    #pragma unroll
    for (int qi = 0; qi < 2; qi++) {
        const int q = qi ? (TT - 1 - tid) : tid;
        const float q0 = q_s[qi][0];
        const float q1 = q_s[qi][1];

        float l = 0.f, o0 = 0.f, o1 = 0.f;
        #pragma unroll 4
        for (int k = 0; k <= q; k++) {
            const float4 kv = sKV[k];
            const float s = fmaf(q1, kv.y, q0 * kv.x);
            const float p = ex2f(s);
            l += p;
            o0 = fmaf(p, kv.z, o0);
            o1 = fmaf(p, kv.w, o1);
        }
        const float inv = 1.0f / l;
        Op[(tbase + q) * HH + h] = make_float2(o0 * inv, o1 * inv);
    }
}

// ---------------------------------------------------------------------------
// Output projection: out = AO @ Wo^T, using WoT (coalesced, L1-resident).
// 128 blocks x 256 threads; 16 AO rows per block; warp handles 2 rows,
// lane owns 4 consecutive output columns (float4 accumulators).
// ---------------------------------------------------------------------------
__global__ void __launch_bounds__(256) proj_kernel(float* __restrict__ out) {
    __shared__ float sAO[16][DD];     // 8 KB

    const int tid = threadIdx.x;
    const int warp = tid >> 5;
    const int lane = tid & 31;
    const int row0 = blockIdx.x * 16;

    // Stage 16 AO rows (coalesced float4)
    for (int i = tid; i < 16 * 32; i += 256) {
        const int r = i >> 5;
        const int c = i & 31;
        reinterpret_cast<float4*>(sAO[r])[c] =
            reinterpret_cast<const float4*>(g_AO + (row0 + r) * DD)[c];
    }
    __syncthreads();

    const int r0 = warp * 2;
    const int r1 = r0 + 1;
    const int j4 = lane * 4;

    float4 acc0 = make_float4(0.f, 0.f, 0.f, 0.f);
    float4 acc1 = make_float4(0.f, 0.f, 0.f, 0.f);

    #pragma unroll 4
    for (int k = 0; k < DD; k++) {
        const float4 wv = *reinterpret_cast<const float4*>(g_WoT + k * DD + j4);
        const float a0 = sAO[r0][k];
        const float a1 = sAO[r1][k];
        acc0.x = fmaf(a0, wv.x, acc0.x);
        acc0.y = fmaf(a0, wv.y, acc0.y);
        acc0.z = fmaf(a0, wv.z, acc0.z);
        acc0.w = fmaf(a0, wv.w, acc0.w);
        acc1.x = fmaf(a1, wv.x, acc1.x);
        acc1.y = fmaf(a1, wv.y, acc1.y);
        acc1.z = fmaf(a1, wv.z, acc1.z);
        acc1.w = fmaf(a1, wv.w, acc1.w);
    }

    *reinterpret_cast<float4*>(out + (row0 + r0) * DD + j4) = acc0;
    *reinterpret_cast<float4*>(out + (row0 + r1) * DD + j4) = acc1;
}

extern "C" void kernel_launch(void* const* d_in, const int* in_sizes, int n_in,
                              void* d_out, int out_size) {
    const float* x  = (const float*)d_in[0];
    const float* Wq = (const float*)d_in[1];
    const float* Wk = (const float*)d_in[2];
    const float* Wv = (const float*)d_in[3];
    const float* Wo = (const float*)d_in[4];
    float* out = (float*)d_out;

    transpose_kernel<<<dim3(68, 4), dim3(32, 8)>>>(x, Wo);
    fused_attn_kernel<<<BB * HH, 512>>>(Wq, Wk, Wv);
    proj_kernel<<<128, 256>>>(out);
}

// round 4
// speedup vs baseline: 3.5832x; 3.5832x over previous
#include <cuda_runtime.h>
#include <math.h>

#define BB 2
#define TT 1024
#define DD 128
#define HH 64
// DH = 2

// Scratch (allocation-free contract: __device__ globals)
__device__ float g_WT[4][DD * DD];          // transposed Wq, Wk, Wv, Wo
__device__ float g_Qh[BB * HH * TT * 2];    // Q head-major: [(b*64+h)*1024+t] float2
__device__ float g_KV[BB * HH * TT * 4];    // K/V interleaved: (k0,k1,v0,v1) per (b,h,t)
__device__ float g_AO[BB * TT * DD];        // attention out, row-major [t_glob][d]

__device__ __forceinline__ float ex2f(float x) {
    float y;
    asm("ex2.approx.ftz.f32 %0, %1;" : "=f"(y) : "f"(x));
    return y;
}

// ---------------------------------------------------------------------------
// Weight transpose: g_WT[z][k][j] = W_z[j][k], four 128x128 matrices.
// grid (4,4,4): z = matrix, (x,y) = 32x32 tile. block (32,8).
// ---------------------------------------------------------------------------
__global__ void __launch_bounds__(256) wtrans_kernel(const float* __restrict__ Wq,
                                                     const float* __restrict__ Wk,
                                                     const float* __restrict__ Wv,
                                                     const float* __restrict__ Wo) {
    __shared__ float t[32][33];
    const float* src = (blockIdx.z == 0) ? Wq : (blockIdx.z == 1) ? Wk
                     : (blockIdx.z == 2) ? Wv : Wo;
    float* dst = g_WT[blockIdx.z];
    const int row0 = blockIdx.x * 32;
    const int col0 = blockIdx.y * 32;
    const int tx = threadIdx.x, ty = threadIdx.y;

    #pragma unroll
    for (int i = 0; i < 4; i++)
        t[ty + 8 * i][tx] = src[(row0 + ty + 8 * i) * DD + col0 + tx];
    __syncthreads();
    #pragma unroll
    for (int i = 0; i < 4; i++)
        dst[(col0 + ty + 8 * i) * DD + row0 + tx] = t[tx][ty + 8 * i];
}

// ---------------------------------------------------------------------------
// QKV projection, proj-style: grid (128, 3), 256 threads.
// Block stages 16 x-rows in smem; each warp computes 2 rows x 128 cols,
// lane owns 4 consecutive cols (float4 weight loads from g_WT, L1/L2-resident).
// Writes directly into head-major Q / interleaved KV layouts.
// ---------------------------------------------------------------------------
__global__ void __launch_bounds__(256) qkv_kernel(const float* __restrict__ x) {
    __shared__ float sX[16][DD];   // 8 KB

    const int tid = threadIdx.x;
    const int warp = tid >> 5;
    const int lane = tid & 31;
    const int row0 = blockIdx.x * 16;
    const int z = blockIdx.y;                 // 0=Q, 1=K, 2=V
    const float* __restrict__ WT = g_WT[z];

    for (int i = tid; i < 16 * 32; i += 256) {
        const int r = i >> 5, c = i & 31;
        reinterpret_cast<float4*>(sX[r])[c] =
            reinterpret_cast<const float4*>(x + (row0 + r) * DD)[c];
    }
    __syncthreads();

    const int r0 = row0 + warp * 2;
    const int j4 = lane * 4;

    float4 acc0 = make_float4(0.f, 0.f, 0.f, 0.f);
    float4 acc1 = make_float4(0.f, 0.f, 0.f, 0.f);

    #pragma unroll 4
    for (int k = 0; k < DD; k++) {
        const float4 wv = *reinterpret_cast<const float4*>(WT + k * DD + j4);
        const float a0 = sX[warp * 2][k];
        const float a1 = sX[warp * 2 + 1][k];
        acc0.x = fmaf(a0, wv.x, acc0.x);
        acc0.y = fmaf(a0, wv.y, acc0.y);
        acc0.z = fmaf(a0, wv.z, acc0.z);
        acc0.w = fmaf(a0, wv.w, acc0.w);
        acc1.x = fmaf(a1, wv.x, acc1.x);
        acc1.y = fmaf(a1, wv.y, acc1.y);
        acc1.z = fmaf(a1, wv.z, acc1.z);
        acc1.w = fmaf(a1, wv.w, acc1.w);
    }

    // Scatter into head-major layouts. cols j4..j4+3 = heads h0, h0+1.
    const int b = r0 >> 10;
    const int t0 = r0 & 1023;
    const int h0 = j4 >> 1;
    const int i00 = (b * HH + h0) * TT + t0;       // (b, h0, t0)
    const int i10 = (b * HH + h0 + 1) * TT + t0;   // (b, h0+1, t0)

    if (z == 0) {
        float2* __restrict__ Qp = reinterpret_cast<float2*>(g_Qh);
        Qp[i00]     = make_float2(acc0.x, acc0.y);
        Qp[i10]     = make_float2(acc0.z, acc0.w);
        Qp[i00 + 1] = make_float2(acc1.x, acc1.y);
        Qp[i10 + 1] = make_float2(acc1.z, acc1.w);
    } else {
        const int off = (z == 1) ? 0 : 2;          // K -> .xy, V -> .zw
        float2* __restrict__ KVp = reinterpret_cast<float2*>(g_KV + off);
        KVp[i00 * 2]       = make_float2(acc0.x, acc0.y);
        KVp[i10 * 2]       = make_float2(acc0.z, acc0.w);
        KVp[(i00 + 1) * 2] = make_float2(acc1.x, acc1.y);
        KVp[(i10 + 1) * 2] = make_float2(acc1.z, acc1.w);
    }
}

// ---------------------------------------------------------------------------
// Causal attention, DH=2. One block per (b,h), 512 threads.
// Thread tid owns queries {tid, 1023-tid} (1025 keys -> perfectly balanced).
// Single-pass softmax (no max subtraction; scores bounded, 2^m rescale exact).
// K/V as one float4 per key in smem -> 1 broadcast LDS.128 per key.
// ---------------------------------------------------------------------------
__global__ void __launch_bounds__(512) attn_kernel() {
    __shared__ float4 sKV[TT];   // 16 KB

    const int tid = threadIdx.x;
    const int bh = blockIdx.x;                // b*64 + h
    const int b = bh >> 6;
    const int h = bh & 63;

    const float4* __restrict__ KVp = reinterpret_cast<const float4*>(g_KV) + bh * TT;
    const float2* __restrict__ Qp  = reinterpret_cast<const float2*>(g_Qh) + bh * TT;

    sKV[tid]       = KVp[tid];
    sKV[tid + 512] = KVp[tid + 512];
    __syncthreads();

    // fold 1/(sqrt(DH)*temperature) and log2(e) into the query
    const float cf = 1.4426950408889634f / (1.4142135623730951f * 0.8f);
    float2* __restrict__ Op = reinterpret_cast<float2*>(g_AO);

    #pragma unroll
    for (int qi = 0; qi < 2; qi++) {
        const int q = qi ? (TT - 1 - tid) : tid;
        const float2 qv = Qp[q];
        const float q0 = qv.x * cf;
        const float q1 = qv.y * cf;

        float l = 0.f, o0 = 0.f, o1 = 0.f;
        #pragma unroll 4
        for (int k = 0; k <= q; k++) {
            const float4 kv = sKV[k];
            const float s = fmaf(q1, kv.y, q0 * kv.x);
            const float p = ex2f(s);
            l += p;
            o0 = fmaf(p, kv.z, o0);
            o1 = fmaf(p, kv.w, o1);
        }
        const float inv = 1.0f / l;
        Op[(b * TT + q) * HH + h] = make_float2(o0 * inv, o1 * inv);
    }
}

// ---------------------------------------------------------------------------
// Output projection: out = AO @ Wo^T via g_WT[3] (measured ~3us pattern).
// ---------------------------------------------------------------------------
__global__ void __launch_bounds__(256) proj_kernel(float* __restrict__ out) {
    __shared__ float sAO[16][DD];   // 8 KB

    const int tid = threadIdx.x;
    const int warp = tid >> 5;
    const int lane = tid & 31;
    const int row0 = blockIdx.x * 16;
    const float* __restrict__ WoT = g_WT[3];

    for (int i = tid; i < 16 * 32; i += 256) {
        const int r = i >> 5, c = i & 31;
        reinterpret_cast<float4*>(sAO[r])[c] =
            reinterpret_cast<const float4*>(g_AO + (row0 + r) * DD)[c];
    }
    __syncthreads();

    const int r0 = warp * 2;
    const int r1 = r0 + 1;
    const int j4 = lane * 4;

    float4 acc0 = make_float4(0.f, 0.f, 0.f, 0.f);
    float4 acc1 = make_float4(0.f, 0.f, 0.f, 0.f);

    #pragma unroll 4
    for (int k = 0; k < DD; k++) {
        const float4 wv = *reinterpret_cast<const float4*>(WoT + k * DD + j4);
        const float a0 = sAO[r0][k];
        const float a1 = sAO[r1][k];
        acc0.x = fmaf(a0, wv.x, acc0.x);
        acc0.y = fmaf(a0, wv.y, acc0.y);
        acc0.z = fmaf(a0, wv.z, acc0.z);
        acc0.w = fmaf(a0, wv.w, acc0.w);
        acc1.x = fmaf(a1, wv.x, acc1.x);
        acc1.y = fmaf(a1, wv.y, acc1.y);
        acc1.z = fmaf(a1, wv.z, acc1.z);
        acc1.w = fmaf(a1, wv.w, acc1.w);
    }

    *reinterpret_cast<float4*>(out + (row0 + r0) * DD + j4) = acc0;
    *reinterpret_cast<float4*>(out + (row0 + r1) * DD + j4) = acc1;
}

extern "C" void kernel_launch(void* const* d_in, const int* in_sizes, int n_in,
                              void* d_out, int out_size) {
    const float* x  = (const float*)d_in[0];
    const float* Wq = (const float*)d_in[1];
    const float* Wk = (const float*)d_in[2];
    const float* Wv = (const float*)d_in[3];
    const float* Wo = (const float*)d_in[4];
    float* out = (float*)d_out;

    wtrans_kernel<<<dim3(4, 4, 4), dim3(32, 8)>>>(Wq, Wk, Wv, Wo);
    qkv_kernel<<<dim3(128, 3), 256>>>(x);
    attn_kernel<<<BB * HH, 512>>>();
    proj_kernel<<<128, 256>>>(out);
}

// round 5
// speedup vs baseline: 5.1312x; 1.4320x over previous
#include <cuda_runtime.h>
#include <math.h>

#define BB 2
#define TT 1024
#define DD 128
#define HH 64
// DH = 2

// Scratch (allocation-free contract: __device__ globals)
__device__ float g_WT[4][DD * DD];          // transposed Wq, Wk, Wv, Wo
__device__ float g_Qh[BB * HH * TT * 2];    // Q head-major: [(b*64+h)*1024+t] float2
__device__ float g_KV[BB * HH * TT * 4];    // K/V interleaved: (k0,k1,v0,v1) per (b,h,t)
__device__ float g_AO[BB * TT * DD];        // attention out, row-major [t_glob][d]

__device__ __forceinline__ float ex2f(float x) {
    float y;
    asm("ex2.approx.ftz.f32 %0, %1;" : "=f"(y) : "f"(x));
    return y;
}

// ---------------------------------------------------------------------------
// Weight transpose: g_WT[z][k][j] = W_z[j][k], four 128x128 matrices.
// grid (4,4,4): z = matrix, (x,y) = 32x32 tile. block (32,8).
// ---------------------------------------------------------------------------
__global__ void __launch_bounds__(256) wtrans_kernel(const float* __restrict__ Wq,
                                                     const float* __restrict__ Wk,
                                                     const float* __restrict__ Wv,
                                                     const float* __restrict__ Wo) {
    __shared__ float t[32][33];
    const float* src = (blockIdx.z == 0) ? Wq : (blockIdx.z == 1) ? Wk
                     : (blockIdx.z == 2) ? Wv : Wo;
    float* dst = g_WT[blockIdx.z];
    const int row0 = blockIdx.x * 32;
    const int col0 = blockIdx.y * 32;
    const int tx = threadIdx.x, ty = threadIdx.y;

    #pragma unroll
    for (int i = 0; i < 4; i++)
        t[ty + 8 * i][tx] = src[(row0 + ty + 8 * i) * DD + col0 + tx];
    __syncthreads();
    #pragma unroll
    for (int i = 0; i < 4; i++)
        dst[(col0 + ty + 8 * i) * DD + row0 + tx] = t[tx][ty + 8 * i];
}

// ---------------------------------------------------------------------------
// Shared GEMM core: 16 rows of A (in sX) times WT (staged in 2 k-chunks of
// 32 KB in sW). All compute-loop operands come from smem: broadcast LDS for
// the A values, conflict-free LDS.128 for the weights. Returns the two
// float4 accumulators for (warp's 2 rows) x (lane's 4 cols).
// ---------------------------------------------------------------------------
struct Acc2 { float4 a0, a1; };

__device__ __forceinline__ Acc2 gemm16(const float* __restrict__ A,
                                       const float* __restrict__ WT,
                                       int row0,
                                       float sX[16][DD],
                                       float sW[64][DD]) {
    const int tid = threadIdx.x;
    const int warp = tid >> 5;
    const int lane = tid & 31;
    const int j4 = lane * 4;

    // Stage 16 A rows (coalesced float4, 8 independent loads/thread)
    #pragma unroll
    for (int i = 0; i < 2; i++) {
        const int idx = tid + i * 256;          // 512 float4 total
        const int r = idx >> 5, c = idx & 31;
        reinterpret_cast<float4*>(sX[r])[c] =
            reinterpret_cast<const float4*>(A + (row0 + r) * DD)[c];
    }

    float4 acc0 = make_float4(0.f, 0.f, 0.f, 0.f);
    float4 acc1 = make_float4(0.f, 0.f, 0.f, 0.f);

    #pragma unroll
    for (int kc = 0; kc < 2; kc++) {
        __syncthreads();
        // Stage weight k-chunk: 64 rows x 128 floats = 2048 float4, linear copy
        {
            const float4* __restrict__ src =
                reinterpret_cast<const float4*>(WT + kc * 64 * DD);
            float4* __restrict__ dst = reinterpret_cast<float4*>(&sW[0][0]);
            #pragma unroll
            for (int i = 0; i < 8; i++)
                dst[tid + i * 256] = src[tid + i * 256];
        }
        __syncthreads();

        #pragma unroll 8
        for (int kk = 0; kk < 64; kk++) {
            const int k = kc * 64 + kk;
            const float4 wv = *reinterpret_cast<const float4*>(&sW[kk][j4]);
            const float a0 = sX[warp * 2][k];
            const float a1 = sX[warp * 2 + 1][k];
            acc0.x = fmaf(a0, wv.x, acc0.x);
            acc0.y = fmaf(a0, wv.y, acc0.y);
            acc0.z = fmaf(a0, wv.z, acc0.z);
            acc0.w = fmaf(a0, wv.w, acc0.w);
            acc1.x = fmaf(a1, wv.x, acc1.x);
            acc1.y = fmaf(a1, wv.y, acc1.y);
            acc1.z = fmaf(a1, wv.z, acc1.z);
            acc1.w = fmaf(a1, wv.w, acc1.w);
        }
    }
    return Acc2{acc0, acc1};
}

// ---------------------------------------------------------------------------
// QKV projection: grid (128, 3), 256 threads. Writes head-major Q /
// interleaved KV directly.
// ---------------------------------------------------------------------------
__global__ void __launch_bounds__(256) qkv_kernel(const float* __restrict__ x) {
    __shared__ float sX[16][DD];   // 8 KB
    __shared__ float sW[64][DD];   // 32 KB

    const int tid = threadIdx.x;
    const int warp = tid >> 5;
    const int lane = tid & 31;
    const int row0 = blockIdx.x * 16;
    const int z = blockIdx.y;                 // 0=Q, 1=K, 2=V

    Acc2 acc = gemm16(x, g_WT[z], row0, sX, sW);

    // Scatter into head-major layouts. Lane's cols j4..j4+3 = heads h0, h0+1.
    const int r0 = row0 + warp * 2;
    const int b = r0 >> 10;
    const int t0 = r0 & 1023;
    const int h0 = lane * 2;
    const int i00 = (b * HH + h0) * TT + t0;
    const int i10 = (b * HH + h0 + 1) * TT + t0;

    if (z == 0) {
        float2* __restrict__ Qp = reinterpret_cast<float2*>(g_Qh);
        Qp[i00]     = make_float2(acc.a0.x, acc.a0.y);
        Qp[i10]     = make_float2(acc.a0.z, acc.a0.w);
        Qp[i00 + 1] = make_float2(acc.a1.x, acc.a1.y);
        Qp[i10 + 1] = make_float2(acc.a1.z, acc.a1.w);
    } else {
        const int off = (z == 1) ? 0 : 2;     // K -> .xy, V -> .zw
        float2* __restrict__ KVp = reinterpret_cast<float2*>(g_KV + off);
        KVp[i00 * 2]       = make_float2(acc.a0.x, acc.a0.y);
        KVp[i10 * 2]       = make_float2(acc.a0.z, acc.a0.w);
        KVp[(i00 + 1) * 2] = make_float2(acc.a1.x, acc.a1.y);
        KVp[(i10 + 1) * 2] = make_float2(acc.a1.z, acc.a1.w);
    }
}

// ---------------------------------------------------------------------------
// Causal attention, DH=2. One block per (b,h), 512 threads.
// Thread tid owns queries {tid, 1023-tid} (1025 keys -> balanced).
// Single-pass softmax (no max subtraction; scores bounded, rescale exact).
// K/V as one float4 per key in smem -> 1 broadcast LDS.128 per key.
// ---------------------------------------------------------------------------
__global__ void __launch_bounds__(512) attn_kernel() {
    __shared__ float4 sKV[TT];   // 16 KB

    const int tid = threadIdx.x;
    const int bh = blockIdx.x;                // b*64 + h
    const int b = bh >> 6;
    const int h = bh & 63;

    const float4* __restrict__ KVp = reinterpret_cast<const float4*>(g_KV) + bh * TT;
    const float2* __restrict__ Qp  = reinterpret_cast<const float2*>(g_Qh) + bh * TT;

    sKV[tid]       = KVp[tid];
    sKV[tid + 512] = KVp[tid + 512];
    __syncthreads();

    // fold 1/(sqrt(DH)*temperature) and log2(e) into the query
    const float cf = 1.4426950408889634f / (1.4142135623730951f * 0.8f);
    float2* __restrict__ Op = reinterpret_cast<float2*>(g_AO);

    #pragma unroll
    for (int qi = 0; qi < 2; qi++) {
        const int q = qi ? (TT - 1 - tid) : tid;
        const float2 qv = Qp[q];
        const float q0 = qv.x * cf;
        const float q1 = qv.y * cf;

        float l = 0.f, o0 = 0.f, o1 = 0.f;
        #pragma unroll 4
        for (int k = 0; k <= q; k++) {
            const float4 kv = sKV[k];
            const float s = fmaf(q1, kv.y, q0 * kv.x);
            const float p = ex2f(s);
            l += p;
            o0 = fmaf(p, kv.z, o0);
            o1 = fmaf(p, kv.w, o1);
        }
        const float inv = 1.0f / l;
        Op[(b * TT + q) * HH + h] = make_float2(o0 * inv, o1 * inv);
    }
}

// ---------------------------------------------------------------------------
// Output projection: out = AO @ Wo^T via g_WT[3], smem-staged weights.
// ---------------------------------------------------------------------------
__global__ void __launch_bounds__(256) proj_kernel(float* __restrict__ out) {
    __shared__ float sX[16][DD];   // 8 KB
    __shared__ float sW[64][DD];   // 32 KB

    const int tid = threadIdx.x;
    const int warp = tid >> 5;
    const int lane = tid & 31;
    const int row0 = blockIdx.x * 16;

    Acc2 acc = gemm16(g_AO, g_WT[3], row0, sX, sW);

    const int r0 = row0 + warp * 2;
    const int j4 = lane * 4;
    *reinterpret_cast<float4*>(out + r0 * DD + j4)       = acc.a0;
    *reinterpret_cast<float4*>(out + (r0 + 1) * DD + j4) = acc.a1;
}

extern "C" void kernel_launch(void* const* d_in, const int* in_sizes, int n_in,
                              void* d_out, int out_size) {
    const float* x  = (const float*)d_in[0];
    const float* Wq = (const float*)d_in[1];
    const float* Wk = (const float*)d_in[2];
    const float* Wv = (const float*)d_in[3];
    const float* Wo = (const float*)d_in[4];
    float* out = (float*)d_out;

    wtrans_kernel<<<dim3(4, 4, 4), dim3(32, 8)>>>(Wq, Wk, Wv, Wo);
    qkv_kernel<<<dim3(128, 3), 256>>>(x);
    attn_kernel<<<BB * HH, 512>>>();
    proj_kernel<<<128, 256>>>(out);
}